// round 7
// baseline (speedup 1.0000x reference)
#include <cuda_runtime.h>
#include <math.h>

// Problem constants
#define NTOT   65536      // B*H*W flattened vectors
#define KCB    1024       // codebook size
#define DD     64         // embedding dim
#define KCHUNK 128        // K-chunk cached in smem per pass
#define HWSZ   1024       // H*W

// Output layout (concatenated flattened outputs, f32):
// [0]                      loss
// [1 .. 4194304]           quant_out (NCHW)        (base ≡ 4 mod 16 bytes)
// [4194305]                perplexity
// [4194306 .. +67108863]   encodings (N x K)       (base ≡ 8 mod 16 bytes)
// [71303170 .. +65535]     idx (as float)
#define OFF_QUANT 1
#define QUANT_SZ  4194304
#define OFF_PERP  (1 + QUANT_SZ)
#define OFF_ENC   (2 + QUANT_SZ)
#define ENC_SZ    67108864
#define OFF_IDX   (2 + QUANT_SZ + ENC_SZ)
#define OUT_TOTAL (2 + QUANT_SZ + ENC_SZ + NTOT)

// Device scratch (no allocations allowed)
__device__ int    g_idx[NTOT];
__device__ int    g_counts[KCB];
__device__ float  g_e2[KCB];
__device__ double g_mse;

// ---- packed f32x2 helpers (sm_103a) -------------------------------------
static __device__ __forceinline__ unsigned long long ffma2(
    unsigned long long a, unsigned long long b, unsigned long long c) {
    unsigned long long d;
    asm("fma.rn.f32x2 %0, %1, %2, %3;" : "=l"(d) : "l"(a), "l"(b), "l"(c));
    return d;
}
static __device__ __forceinline__ unsigned long long fadd2(
    unsigned long long a, unsigned long long b) {
    unsigned long long d;
    asm("add.rn.f32x2 %0, %1, %2;" : "=l"(d) : "l"(a), "l"(b));
    return d;
}
static __device__ __forceinline__ unsigned long long pack2(float a, float b) {
    unsigned long long p;
    asm("mov.b64 %0, {%1, %2};" : "=l"(p) : "f"(a), "f"(b));
    return p;
}
static __device__ __forceinline__ float unpack_sum(unsigned long long v) {
    float lo, hi;
    asm("mov.b64 {%0, %1}, %2;" : "=f"(lo), "=f"(hi) : "l"(v));
    return lo + hi;
}

// ---- kernel 0: e2 precompute + zero scratch -----------------------------
__global__ void prep_kernel(const float* __restrict__ emb) {
    int t = blockIdx.x * blockDim.x + threadIdx.x;
    if (t < KCB) {
        const float4* e4 = reinterpret_cast<const float4*>(emb + t * DD);
        float s = 0.f;
        #pragma unroll
        for (int j = 0; j < 16; j++) {
            float4 v = e4[j];
            s += v.x * v.x; s += v.y * v.y; s += v.z * v.z; s += v.w * v.w;
        }
        g_e2[t] = s;
        g_counts[t] = 0;
    }
    if (t == 0) g_mse = 0.0;
}

// ---- kernel 1: fused distance + argmin ----------------------------------
// One thread per n. x in 32 packed f32x2 regs; emb chunk (128x64) in smem,
// broadcast LDS.128; inner product via fma.rn.f32x2 (4 indep accumulators).
__global__ void __launch_bounds__(256, 2)
argmin_kernel(const float* __restrict__ inp, const float* __restrict__ emb) {
    __shared__ __align__(16) float es[KCHUNK * DD];   // 32 KB
    __shared__ float e2s[KCHUNK];

    int n = blockIdx.x * 256 + threadIdx.x;
    int b = n >> 10;
    int p = n & 1023;
    const float* xb = inp + (size_t)b * (DD * HWSZ) + p;   // stride 1024 over d

    unsigned long long xp[DD / 2];
    float x2 = 0.f;
    #pragma unroll
    for (int j = 0; j < DD / 2; j++) {
        float a = xb[(2 * j) * HWSZ];
        float c = xb[(2 * j + 1) * HWSZ];
        x2 += a * a;
        x2 += c * c;
        xp[j] = pack2(a, c);
    }

    float best = 3.4e38f;
    int bestk = 0;

    for (int c = 0; c < KCB / KCHUNK; c++) {
        __syncthreads();
        {   // cooperative chunk load: 2048 float4s, 8 per thread, coalesced
            const float4* src = reinterpret_cast<const float4*>(emb + c * KCHUNK * DD);
            float4* dst = reinterpret_cast<float4*>(es);
            #pragma unroll
            for (int i = 0; i < 8; i++)
                dst[threadIdx.x + i * 256] = src[threadIdx.x + i * 256];
            if (threadIdx.x < KCHUNK)
                e2s[threadIdx.x] = g_e2[c * KCHUNK + threadIdx.x];
        }
        __syncthreads();

        #pragma unroll 2
        for (int k = 0; k < KCHUNK; k++) {
            const ulonglong2* ev = reinterpret_cast<const ulonglong2*>(es + k * DD);
            unsigned long long a0 = 0ull, a1 = 0ull, a2 = 0ull, a3 = 0ull;
            #pragma unroll
            for (int j = 0; j < 8; j++) {
                ulonglong2 e01 = ev[2 * j];
                ulonglong2 e23 = ev[2 * j + 1];
                a0 = ffma2(xp[4 * j + 0], e01.x, a0);
                a1 = ffma2(xp[4 * j + 1], e01.y, a1);
                a2 = ffma2(xp[4 * j + 2], e23.x, a2);
                a3 = ffma2(xp[4 * j + 3], e23.y, a3);
            }
            unsigned long long s = fadd2(fadd2(a0, a1), fadd2(a2, a3));
            float dot = unpack_sum(s);
            float t = x2 + e2s[k];
            float dist = fmaf(dot, -2.0f, t);   // 2*dot is exact; single rounding
            if (dist < best) { best = dist; bestk = c * KCHUNK + k; }
        }
    }
    g_idx[n] = bestk;
}

// ---- kernel 2: scatter ones, idx output, histogram ----------------------
// Runs AFTER the memset of the encodings region (separate launch => ordered).
__global__ void scatter_kernel(float* __restrict__ enc, float* __restrict__ oidx) {
    int n = blockIdx.x * blockDim.x + threadIdx.x;
    int k = g_idx[n];
    atomicAdd(&g_counts[k], 1);
    enc[(size_t)n * KCB + k] = 1.0f;
    oidx[n] = (float)k;
}

// ---- kernel 3: quantized output (straight-through) + MSE ----------------
// 4 elements per thread. Quant base is 4 mod 16 bytes -> peel 3 elements so
// the vector stores land 16B-aligned (elements 3 + 4t), tail element at end.
// Each thread issues 4 independent g_idx/emb gathers (MLP=4+).
__global__ void __launch_bounds__(1024)
quant_mse_kernel(const float* __restrict__ inp,
                 const float* __restrict__ emb,
                 float* __restrict__ oq) {
    int t = blockIdx.x * blockDim.x + threadIdx.x;   // [0, 1048576)
    int e0 = 3 + 4 * t;                              // first of 4 elements

    float sq = 0.f;
    float vx[4], vq[4];
    #pragma unroll
    for (int j = 0; j < 4; j++) {
        int e = e0 + j;
        int b = e >> 16;
        int r = e & 65535;
        int d = r >> 10;
        int p = r & 1023;
        int n = (b << 10) | p;
        vq[j] = emb[g_idx[n] * DD + d];
        vx[j] = inp[e];
    }
    float4 o;
    {
        float d0 = vq[0] - vx[0], d1 = vq[1] - vx[1];
        float d2 = vq[2] - vx[2], d3 = vq[3] - vx[3];
        o.x = vx[0] + d0; o.y = vx[1] + d1;
        o.z = vx[2] + d2; o.w = vx[3] + d3;
        sq = d0 * d0 + d1 * d1 + d2 * d2 + d3 * d3;
    }
    *reinterpret_cast<float4*>(oq + e0) = o;         // 16B aligned

    // peel/tail: elements 0,1,2 and QUANT_SZ-1, handled by thread 0
    if (t == 0) {
        const int extra[4] = {0, 1, 2, QUANT_SZ - 1};
        #pragma unroll
        for (int j = 0; j < 4; j++) {
            int e = extra[j];
            int b = e >> 16;
            int r = e & 65535;
            int d = r >> 10;
            int p = r & 1023;
            int n = (b << 10) | p;
            float q = emb[g_idx[n] * DD + d];
            float x = inp[e];
            float df = q - x;
            oq[e] = x + df;
            sq += df * df;
        }
    }

    // block reduction -> double atomic
    #pragma unroll
    for (int o2 = 16; o2 > 0; o2 >>= 1)
        sq += __shfl_down_sync(0xffffffffu, sq, o2);
    __shared__ float warpsum[32];
    int lane = threadIdx.x & 31, wid = threadIdx.x >> 5;
    if (lane == 0) warpsum[wid] = sq;
    __syncthreads();
    if (wid == 0) {
        float v = (lane < (blockDim.x >> 5)) ? warpsum[lane] : 0.f;
        #pragma unroll
        for (int o2 = 16; o2 > 0; o2 >>= 1)
            v += __shfl_down_sync(0xffffffffu, v, o2);
        if (lane == 0) atomicAdd(&g_mse, (double)v);
    }
}

// ---- kernel 4: perplexity + loss ----------------------------------------
__global__ void finalize_kernel(float* __restrict__ out) {
    int t = threadIdx.x;   // 1024 threads
    float pr = (float)g_counts[t] * (1.0f / 65536.0f);
    float term = pr * logf(pr + 1e-10f);
    double s = (double)term;
    #pragma unroll
    for (int o = 16; o > 0; o >>= 1)
        s += __shfl_down_sync(0xffffffffu, s, o);
    __shared__ double wsum[32];
    int lane = t & 31, wid = t >> 5;
    if (lane == 0) wsum[wid] = s;
    __syncthreads();
    if (wid == 0) {
        double v = (lane < 32) ? wsum[lane] : 0.0;
        #pragma unroll
        for (int o = 16; o > 0; o >>= 1)
            v += __shfl_down_sync(0xffffffffu, v, o);
        if (lane == 0) {
            float perp = expf(-(float)v);
            float mse = (float)(g_mse * (1.0 / 4194304.0));
            // loss = q_latent + COMMIT*e_latent + diversity ; both latents == mse
            float loss = mse + 0.25f * mse + 0.1f * ((1024.0f - perp) / 1024.0f);
            out[0] = loss;
            out[OFF_PERP] = perp;
        }
    }
}

extern "C" void kernel_launch(void* const* d_in, const int* in_sizes, int n_in,
                              void* d_out, int out_size) {
    const float* inp = (const float*)d_in[0];
    const float* emb = (const float*)d_in[1];
    // defensive: detect swapped input order by element counts
    if (n_in >= 2 && in_sizes[0] == KCB * DD && in_sizes[1] == QUANT_SZ) {
        const float* t = inp; inp = emb; emb = t;
    }
    float* out = (float*)d_out;

    prep_kernel<<<4, 256>>>(emb);

    if (out_size >= OUT_TOTAL) {
        float* o_quant = out + OFF_QUANT;
        float* o_enc   = out + OFF_ENC;
        float* o_idx   = out + OFF_IDX;

        // bulk-zero the encodings region at driver-memset bandwidth
        // (graph-capturable: no allocation, async, device-side)
        cudaMemsetAsync(o_enc, 0, (size_t)ENC_SZ * sizeof(float));

        argmin_kernel<<<NTOT / 256, 256>>>(inp, emb);
        scatter_kernel<<<NTOT / 256, 256>>>(o_enc, o_idx);
        quant_mse_kernel<<<QUANT_SZ / 4096, 1024>>>(inp, emb, o_quant);
        finalize_kernel<<<1, 1024>>>(out);
    } else if (out_size == QUANT_SZ) {
        // fallback layout: quant_out only
        argmin_kernel<<<NTOT / 256, 256>>>(inp, emb);
        quant_mse_kernel<<<QUANT_SZ / 4096, 1024>>>(inp, emb, out);
    } else {
        // unknown layout: still produce argmin + scalars at best effort
        argmin_kernel<<<NTOT / 256, 256>>>(inp, emb);
        finalize_kernel<<<1, 1024>>>(out);
    }
}

// round 8
// speedup vs baseline: 1.0708x; 1.0708x over previous
#include <cuda_runtime.h>
#include <math.h>

// Problem constants
#define NTOT   65536      // B*H*W flattened vectors
#define KCB    1024       // codebook size
#define DD     64         // embedding dim
#define KCHUNK 128        // K-chunk cached in smem per pass
#define HWSZ   1024       // H*W

// Output layout (concatenated flattened outputs, f32):
// [0]                      loss
// [1 .. 4194304]           quant_out (NCHW)        (base ≡ 4 mod 16 bytes)
// [4194305]                perplexity
// [4194306 .. +67108863]   encodings (N x K)       (base ≡ 8 mod 16 bytes -> float2 max)
// [71303170 .. +65535]     idx (as float)
#define OFF_QUANT 1
#define QUANT_SZ  4194304
#define OFF_PERP  (1 + QUANT_SZ)
#define OFF_ENC   (2 + QUANT_SZ)
#define ENC_SZ    67108864
#define OFF_IDX   (2 + QUANT_SZ + ENC_SZ)
#define OUT_TOTAL (2 + QUANT_SZ + ENC_SZ + NTOT)

// Device scratch (no allocations allowed)
__device__ int    g_idx[NTOT];
__device__ int    g_counts[KCB];
__device__ float  g_e2[KCB];
__device__ double g_mse;

// ---- packed f32x2 helpers (sm_103a) -------------------------------------
static __device__ __forceinline__ unsigned long long ffma2(
    unsigned long long a, unsigned long long b, unsigned long long c) {
    unsigned long long d;
    asm("fma.rn.f32x2 %0, %1, %2, %3;" : "=l"(d) : "l"(a), "l"(b), "l"(c));
    return d;
}
static __device__ __forceinline__ unsigned long long fadd2(
    unsigned long long a, unsigned long long b) {
    unsigned long long d;
    asm("add.rn.f32x2 %0, %1, %2;" : "=l"(d) : "l"(a), "l"(b));
    return d;
}
static __device__ __forceinline__ unsigned long long pack2(float a, float b) {
    unsigned long long p;
    asm("mov.b64 %0, {%1, %2};" : "=l"(p) : "f"(a), "f"(b));
    return p;
}
static __device__ __forceinline__ float unpack_sum(unsigned long long v) {
    float lo, hi;
    asm("mov.b64 {%0, %1}, %2;" : "=f"(lo), "=f"(hi) : "l"(v));
    return lo + hi;
}

// ---- kernel 0: e2 precompute + zero scratch -----------------------------
__global__ void prep_kernel(const float* __restrict__ emb) {
    int t = blockIdx.x * blockDim.x + threadIdx.x;
    if (t < KCB) {
        const float4* e4 = reinterpret_cast<const float4*>(emb + t * DD);
        float s = 0.f;
        #pragma unroll
        for (int j = 0; j < 16; j++) {
            float4 v = e4[j];
            s += v.x * v.x; s += v.y * v.y; s += v.z * v.z; s += v.w * v.w;
        }
        g_e2[t] = s;
        g_counts[t] = 0;
    }
    if (t == 0) g_mse = 0.0;
}

// ---- kernel 1: fused distance + argmin ----------------------------------
// One thread per n. x in 32 packed f32x2 regs; emb chunk (128x64) in smem,
// broadcast LDS.128; inner product via fma.rn.f32x2 (4 indep accumulators).
__global__ void __launch_bounds__(256, 2)
argmin_kernel(const float* __restrict__ inp, const float* __restrict__ emb) {
    __shared__ __align__(16) float es[KCHUNK * DD];   // 32 KB
    __shared__ float e2s[KCHUNK];

    int n = blockIdx.x * 256 + threadIdx.x;
    int b = n >> 10;
    int p = n & 1023;
    const float* xb = inp + (size_t)b * (DD * HWSZ) + p;   // stride 1024 over d

    unsigned long long xp[DD / 2];
    float x2 = 0.f;
    #pragma unroll
    for (int j = 0; j < DD / 2; j++) {
        float a = xb[(2 * j) * HWSZ];
        float c = xb[(2 * j + 1) * HWSZ];
        x2 += a * a;
        x2 += c * c;
        xp[j] = pack2(a, c);
    }

    float best = 3.4e38f;
    int bestk = 0;

    for (int c = 0; c < KCB / KCHUNK; c++) {
        __syncthreads();
        {   // cooperative chunk load: 2048 float4s, 8 per thread, coalesced
            const float4* src = reinterpret_cast<const float4*>(emb + c * KCHUNK * DD);
            float4* dst = reinterpret_cast<float4*>(es);
            #pragma unroll
            for (int i = 0; i < 8; i++)
                dst[threadIdx.x + i * 256] = src[threadIdx.x + i * 256];
            if (threadIdx.x < KCHUNK)
                e2s[threadIdx.x] = g_e2[c * KCHUNK + threadIdx.x];
        }
        __syncthreads();

        #pragma unroll 2
        for (int k = 0; k < KCHUNK; k++) {
            const ulonglong2* ev = reinterpret_cast<const ulonglong2*>(es + k * DD);
            unsigned long long a0 = 0ull, a1 = 0ull, a2 = 0ull, a3 = 0ull;
            #pragma unroll
            for (int j = 0; j < 8; j++) {
                ulonglong2 e01 = ev[2 * j];
                ulonglong2 e23 = ev[2 * j + 1];
                a0 = ffma2(xp[4 * j + 0], e01.x, a0);
                a1 = ffma2(xp[4 * j + 1], e01.y, a1);
                a2 = ffma2(xp[4 * j + 2], e23.x, a2);
                a3 = ffma2(xp[4 * j + 3], e23.y, a3);
            }
            unsigned long long s = fadd2(fadd2(a0, a1), fadd2(a2, a3));
            float dot = unpack_sum(s);
            float t = x2 + e2s[k];
            float dist = fmaf(dot, -2.0f, t);   // 2*dot is exact; single rounding
            if (dist < best) { best = dist; bestk = c * KCHUNK + k; }
        }
    }
    g_idx[n] = bestk;
}

// ---- kernel 2: one-hot encodings writer (single pass) + hist + idx ------
// One warp per row n. 16 iterations of coalesced STG.64 (256B per warp-iter),
// value via compare-select. Writes every encodings byte exactly once.
// Lane 0 also emits oidx + histogram atomic.
__global__ void __launch_bounds__(1024)
onehot_kernel(float* __restrict__ enc, float* __restrict__ oidx) {
    int warp = (blockIdx.x * blockDim.x + threadIdx.x) >> 5;   // row n
    int lane = threadIdx.x & 31;
    int k = g_idx[warp];
    float2* row = reinterpret_cast<float2*>(enc) + (size_t)warp * (KCB / 2);

    int c2 = lane * 2;                    // column of .x this iteration
    #pragma unroll
    for (int j = 0; j < 16; j++) {
        float2 v;
        v.x = (c2 == k)     ? 1.0f : 0.0f;
        v.y = (c2 + 1 == k) ? 1.0f : 0.0f;
        row[lane + j * 32] = v;
        c2 += 64;
    }
    if (lane == 0) {
        oidx[warp] = (float)k;
        atomicAdd(&g_counts[k], 1);
    }
}

// ---- kernel 3: quantized output (straight-through) + MSE ----------------
// 4 elements per thread. Quant base is 4 mod 16 bytes -> peel 3 elements so
// the vector stores land 16B-aligned (elements 3 + 4t), tail element at end.
__global__ void __launch_bounds__(1024)
quant_mse_kernel(const float* __restrict__ inp,
                 const float* __restrict__ emb,
                 float* __restrict__ oq) {
    int t = blockIdx.x * blockDim.x + threadIdx.x;   // [0, 1048576)
    int e0 = 3 + 4 * t;                              // first of 4 elements

    float sq = 0.f;
    float vx[4], vq[4];
    #pragma unroll
    for (int j = 0; j < 4; j++) {
        int e = e0 + j;
        int b = e >> 16;
        int r = e & 65535;
        int d = r >> 10;
        int p = r & 1023;
        int n = (b << 10) | p;
        vq[j] = emb[g_idx[n] * DD + d];
        vx[j] = inp[e];
    }
    float4 o;
    {
        float d0 = vq[0] - vx[0], d1 = vq[1] - vx[1];
        float d2 = vq[2] - vx[2], d3 = vq[3] - vx[3];
        o.x = vx[0] + d0; o.y = vx[1] + d1;
        o.z = vx[2] + d2; o.w = vx[3] + d3;
        sq = d0 * d0 + d1 * d1 + d2 * d2 + d3 * d3;
    }
    *reinterpret_cast<float4*>(oq + e0) = o;         // 16B aligned

    // peel/tail: elements 0,1,2 and QUANT_SZ-1, handled by thread 0
    if (t == 0) {
        const int extra[4] = {0, 1, 2, QUANT_SZ - 1};
        #pragma unroll
        for (int j = 0; j < 4; j++) {
            int e = extra[j];
            int b = e >> 16;
            int r = e & 65535;
            int d = r >> 10;
            int p = r & 1023;
            int n = (b << 10) | p;
            float q = emb[g_idx[n] * DD + d];
            float x = inp[e];
            float df = q - x;
            oq[e] = x + df;
            sq += df * df;
        }
    }

    // block reduction -> double atomic
    #pragma unroll
    for (int o2 = 16; o2 > 0; o2 >>= 1)
        sq += __shfl_down_sync(0xffffffffu, sq, o2);
    __shared__ float warpsum[32];
    int lane = threadIdx.x & 31, wid = threadIdx.x >> 5;
    if (lane == 0) warpsum[wid] = sq;
    __syncthreads();
    if (wid == 0) {
        float v = (lane < (blockDim.x >> 5)) ? warpsum[lane] : 0.f;
        #pragma unroll
        for (int o2 = 16; o2 > 0; o2 >>= 1)
            v += __shfl_down_sync(0xffffffffu, v, o2);
        if (lane == 0) atomicAdd(&g_mse, (double)v);
    }
}

// ---- kernel 4: perplexity + loss ----------------------------------------
__global__ void finalize_kernel(float* __restrict__ out) {
    int t = threadIdx.x;   // 1024 threads
    float pr = (float)g_counts[t] * (1.0f / 65536.0f);
    float term = pr * logf(pr + 1e-10f);
    double s = (double)term;
    #pragma unroll
    for (int o = 16; o > 0; o >>= 1)
        s += __shfl_down_sync(0xffffffffu, s, o);
    __shared__ double wsum[32];
    int lane = t & 31, wid = t >> 5;
    if (lane == 0) wsum[wid] = s;
    __syncthreads();
    if (wid == 0) {
        double v = (lane < 32) ? wsum[lane] : 0.0;
        #pragma unroll
        for (int o = 16; o > 0; o >>= 1)
            v += __shfl_down_sync(0xffffffffu, v, o);
        if (lane == 0) {
            float perp = expf(-(float)v);
            float mse = (float)(g_mse * (1.0 / 4194304.0));
            // loss = q_latent + COMMIT*e_latent + diversity ; both latents == mse
            float loss = mse + 0.25f * mse + 0.1f * ((1024.0f - perp) / 1024.0f);
            out[0] = loss;
            out[OFF_PERP] = perp;
        }
    }
}

extern "C" void kernel_launch(void* const* d_in, const int* in_sizes, int n_in,
                              void* d_out, int out_size) {
    const float* inp = (const float*)d_in[0];
    const float* emb = (const float*)d_in[1];
    // defensive: detect swapped input order by element counts
    if (n_in >= 2 && in_sizes[0] == KCB * DD && in_sizes[1] == QUANT_SZ) {
        const float* t = inp; inp = emb; emb = t;
    }
    float* out = (float*)d_out;

    prep_kernel<<<4, 256>>>(emb);

    if (out_size >= OUT_TOTAL) {
        float* o_quant = out + OFF_QUANT;
        float* o_enc   = out + OFF_ENC;
        float* o_idx   = out + OFF_IDX;

        argmin_kernel<<<NTOT / 256, 256>>>(inp, emb);
        // 65536 warps, 32 warps per 1024-thread block -> 2048 blocks
        onehot_kernel<<<NTOT / 32, 1024>>>(o_enc, o_idx);
        quant_mse_kernel<<<QUANT_SZ / 4096, 1024>>>(inp, emb, o_quant);
        finalize_kernel<<<1, 1024>>>(out);
    } else if (out_size == QUANT_SZ) {
        // fallback layout: quant_out only
        argmin_kernel<<<NTOT / 256, 256>>>(inp, emb);
        quant_mse_kernel<<<QUANT_SZ / 4096, 1024>>>(inp, emb, out);
    } else {
        // unknown layout: still produce argmin + scalars at best effort
        argmin_kernel<<<NTOT / 256, 256>>>(inp, emb);
        finalize_kernel<<<1, 1024>>>(out);
    }
}